// round 9
// baseline (speedup 1.0000x reference)
#include <cuda_runtime.h>

// TransducerJoint: h[b,t,u,:] = f[b,t,:] + g[b,u,:] if t < f_len[b] && u < g_len[b] else 0
// B=16, T=256, U=96, H=512 (fp32). Output 805 MB -> pure HBM-write-bound.
// R9: 16KB span per CTA (8 u-rows, best DRAM interleave from R2/R7) AND high
//     occupancy (R8): 256 threads = 2 u-lanes x 128 h4-lanes, 4 u's per thread
//     (32-reg body), launch_bounds(256,8). float4 __stcs, hoisted n_valid.

#define B_ 16
#define T_ 256
#define U_ 96
#define H_ 512
#define H4_ (H_ / 4)      // 128 float4 per H-row
#define U_PER_BLK 8
#define U_PER_THR 4       // each thread: u = ulane*4 .. ulane*4+3 (contiguous quad)

__global__ __launch_bounds__(256, 8) void transducer_joint_kernel(
    const float4* __restrict__ f,      // (B, T, H/4)
    const float4* __restrict__ g,      // (B, U, H/4)
    const int*    __restrict__ f_len,  // (B,)
    const int*    __restrict__ g_len,  // (B,)
    float4*       __restrict__ out)    // (B, T, U, H/4)
{
    const int h4    = threadIdx.x & 127;   // 0..127
    const int ulane = threadIdx.x >> 7;    // 0..1
    const int u0    = blockIdx.x * U_PER_BLK + ulane * U_PER_THR;
    const int t     = blockIdx.y;
    const int b     = blockIdx.z;

    // valid u count within this thread's [u0, u0+4), computed once
    int n_valid = 0;
    if (t < f_len[b]) {
        int r = g_len[b] - u0;
        n_valid = r < 0 ? 0 : (r > U_PER_THR ? U_PER_THR : r);
    }

    // f row chunk: loaded once, reused for this thread's 4 u's
    const float4 f4 = __ldg(f + ((size_t)b * T_ + t) * H4_ + h4);

    const float4* gbase = g + ((size_t)b * U_ + u0) * H4_ + h4;
    float4* obase = out + (((size_t)b * T_ + t) * U_ + u0) * H4_ + h4;

    const float4 zero = make_float4(0.f, 0.f, 0.f, 0.f);

#pragma unroll
    for (int du = 0; du < U_PER_THR; ++du) {
        float4 r = zero;
        if (du < n_valid) {                       // single scalar predicate
            const float4 g4 = __ldg(gbase + (size_t)du * H4_);
            r.x = f4.x + g4.x;
            r.y = f4.y + g4.y;
            r.z = f4.z + g4.z;
            r.w = f4.w + g4.w;
        }
        __stcs(obase + (size_t)du * H4_, r);      // unconditional streaming store
    }
}

extern "C" void kernel_launch(void* const* d_in, const int* in_sizes, int n_in,
                              void* d_out, int out_size)
{
    const float4* f     = (const float4*)d_in[0];
    const float4* g     = (const float4*)d_in[1];
    const int*    f_len = (const int*)d_in[2];
    const int*    g_len = (const int*)d_in[3];
    float4*       out   = (float4*)d_out;

    dim3 grid(U_ / U_PER_BLK, T_, B_);   // (12, 256, 16) = 49152 CTAs
    dim3 block(256);
    transducer_joint_kernel<<<grid, block>>>(f, g, f_len, g_len, out);
}

// round 10
// speedup vs baseline: 1.0141x; 1.0141x over previous
#include <cuda_runtime.h>

// TransducerJoint: h[b,t,u,:] = f[b,t,:] + g[b,u,:] if t < f_len[b] && u < g_len[b] else 0
// B=16, T=256, U=96, H=512 (fp32). Output 805 MB -> pure HBM-write-bound.
// R10: span sweep endpoint: U_PER_BLK=2 (4KB span, 196608 CTAs). R8 body:
//      128 threads, warp-coherent full-row float4 __stcs stores, hoisted
//      n_valid, launch_bounds(128,16) for max concurrent writers.

#define B_ 16
#define T_ 256
#define U_ 96
#define H_ 512
#define H4_ (H_ / 4)      // 128 float4 per H-row
#define U_PER_BLK 2

__global__ __launch_bounds__(H4_, 16) void transducer_joint_kernel(
    const float4* __restrict__ f,      // (B, T, H/4)
    const float4* __restrict__ g,      // (B, U, H/4)
    const int*    __restrict__ f_len,  // (B,)
    const int*    __restrict__ g_len,  // (B,)
    float4*       __restrict__ out)    // (B, T, U, H/4)
{
    const int h4 = threadIdx.x;        // 0..127
    const int u0 = blockIdx.x * U_PER_BLK;
    const int t  = blockIdx.y;
    const int b  = blockIdx.z;

    // valid u count within [u0, u0+2), computed once
    int n_valid = 0;
    if (t < f_len[b]) {
        int r = g_len[b] - u0;
        n_valid = r < 0 ? 0 : (r > U_PER_BLK ? U_PER_BLK : r);
    }

    // f row chunk: loaded once, reused for both u's
    const float4 f4 = __ldg(f + ((size_t)b * T_ + t) * H4_ + h4);

    const float4* gbase = g + ((size_t)b * U_ + u0) * H4_ + h4;
    float4* obase = out + (((size_t)b * T_ + t) * U_ + u0) * H4_ + h4;

    const float4 zero = make_float4(0.f, 0.f, 0.f, 0.f);

#pragma unroll
    for (int du = 0; du < U_PER_BLK; ++du) {
        float4 r = zero;
        if (du < n_valid) {                       // single scalar predicate
            const float4 g4 = __ldg(gbase + (size_t)du * H4_);
            r.x = f4.x + g4.x;
            r.y = f4.y + g4.y;
            r.z = f4.z + g4.z;
            r.w = f4.w + g4.w;
        }
        __stcs(obase + (size_t)du * H4_, r);      // unconditional streaming store
    }
}

extern "C" void kernel_launch(void* const* d_in, const int* in_sizes, int n_in,
                              void* d_out, int out_size)
{
    const float4* f     = (const float4*)d_in[0];
    const float4* g     = (const float4*)d_in[1];
    const int*    f_len = (const int*)d_in[2];
    const int*    g_len = (const int*)d_in[3];
    float4*       out   = (float4*)d_out;

    dim3 grid(U_ / U_PER_BLK, T_, B_);   // (48, 256, 16) = 196608 CTAs
    dim3 block(H4_);                      // 128 threads
    transducer_joint_kernel<<<grid, block>>>(f, g, f_len, g_len, out);
}